// round 11
// baseline (speedup 1.0000x reference)
#include <cuda_runtime.h>
#include <math.h>

#define N_NODES 50000
#define N_EDGES 800000
#define HID 96
#define HEADS 4
#define HD 24
#define NEG_SLOPE 0.2f
#define FULL 0xffffffffu

// ---------------- scratch (no allocations allowed) ----------------
__device__ float g_feat[N_NODES * HID];
__device__ float g_h0[N_NODES * HID];
__device__ float g_h1[N_NODES * HID];
__device__ float g_el[N_NODES * HEADS];
__device__ float g_er[N_NODES * HEADS];
__device__ float g_w[N_EDGES * HEADS];    // fallback path only (deg > 32)
__device__ int   g_row_off[N_NODES + 1];
__device__ int   g_wptr[N_NODES];
__device__ int   g_csr_src[N_EDGES];
__device__ int   g_bsum[64];

// ---------------- CSR build ----------------
__global__ void zero_all_kernel(int* p, int n, float* out96) {
    int i = blockIdx.x * blockDim.x + threadIdx.x;
    if (i < n) p[i] = 0;
    if (i < 96) out96[i] = 0.f;
}

__global__ void count_kernel(const int* __restrict__ dst, int* __restrict__ counts) {
    int e = blockIdx.x * blockDim.x + threadIdx.x;
    if (e < N_EDGES) atomicAdd(&counts[dst[e]], 1);
}

__global__ void scan1_kernel(const int* __restrict__ in, int* __restrict__ out,
                             int* __restrict__ bsum, int n) {
    __shared__ int sh[1024];
    int i = blockIdx.x * 1024 + threadIdx.x;
    int v = (i < n) ? in[i] : 0;
    sh[threadIdx.x] = v;
    __syncthreads();
    for (int off = 1; off < 1024; off <<= 1) {
        int t = (threadIdx.x >= off) ? sh[threadIdx.x - off] : 0;
        __syncthreads();
        sh[threadIdx.x] += t;
        __syncthreads();
    }
    if (i < n) out[i] = sh[threadIdx.x] - v;
    if (threadIdx.x == 1023) bsum[blockIdx.x] = sh[1023];
}

__global__ void scan2_kernel(int* bsum, int nb) {
    __shared__ int sh[64];
    int t = threadIdx.x;
    int v = (t < nb) ? bsum[t] : 0;
    sh[t] = v;
    __syncthreads();
    for (int off = 1; off < 64; off <<= 1) {
        int x = (t >= off) ? sh[t - off] : 0;
        __syncthreads();
        sh[t] += x;
        __syncthreads();
    }
    if (t < nb) bsum[t] = sh[t] - v;
}

__global__ void scan3_kernel(int* __restrict__ row_off, int* __restrict__ wptr,
                             const int* __restrict__ bsum, int n, int total) {
    int i = blockIdx.x * 1024 + threadIdx.x;
    if (i < n) {
        int v = row_off[i] + bsum[i >> 10];
        row_off[i] = v;
        wptr[i] = v;
    }
    if (i == 0) row_off[n] = total;
}

__global__ void scatter_kernel(const int* __restrict__ src, const int* __restrict__ dst,
                               int* __restrict__ wptr, int* __restrict__ csr_src) {
    int e = blockIdx.x * blockDim.x + threadIdx.x;
    if (e < N_EDGES) {
        int p = atomicAdd(&wptr[dst[e]], 1);
        csr_src[p] = src[e];
    }
}

// ---------------- GEMM: C[n,96] = A[n,K] @ W[K,96] ---------------- (R6 proven)
__global__ __launch_bounds__(512) void gemm_kernel(const float* __restrict__ A,
                                                   const float* __restrict__ W,
                                                   float* __restrict__ C, int n, int K) {
    __shared__ float As[128][33];
    __shared__ float Bs[32][96];
    int tid = threadIdx.x;
    int c = tid & 15;
    int r = tid >> 4;
    int row0 = blockIdx.x * 128;
    float acc[4][6] = {};

    for (int k0 = 0; k0 < K; k0 += 32) {
        #pragma unroll
        for (int t = 0; t < 2; t++) {
            int idx = tid + t * 512;
            int row = idx >> 3, kq = idx & 7;
            float4 v = make_float4(0.f, 0.f, 0.f, 0.f);
            if (row0 + row < n) v = *(const float4*)&A[(size_t)(row0 + row) * K + k0 + kq * 4];
            As[row][kq * 4 + 0] = v.x;
            As[row][kq * 4 + 1] = v.y;
            As[row][kq * 4 + 2] = v.z;
            As[row][kq * 4 + 3] = v.w;
        }
        #pragma unroll
        for (int t = 0; t < 6; t++) {
            int idx = tid + t * 512;
            int k = idx / 96, cc = idx - k * 96;
            Bs[k][cc] = W[(size_t)(k0 + k) * 96 + cc];
        }
        __syncthreads();
        #pragma unroll
        for (int kk = 0; kk < 32; kk++) {
            float b[6];
            #pragma unroll
            for (int j = 0; j < 6; j++) b[j] = Bs[kk][c + 16 * j];
            float a[4];
            #pragma unroll
            for (int i = 0; i < 4; i++) a[i] = As[r * 4 + i][kk];
            #pragma unroll
            for (int i = 0; i < 4; i++)
                #pragma unroll
                for (int j = 0; j < 6; j++)
                    acc[i][j] += a[i] * b[j];
        }
        __syncthreads();
    }
    #pragma unroll
    for (int i = 0; i < 4; i++) {
        int row = row0 + r * 4 + i;
        if (row < n) {
            #pragma unroll
            for (int j = 0; j < 6; j++)
                C[(size_t)row * 96 + c + 16 * j] = acc[i][j];
        }
    }
}

// ---------------- per-node attention coefficients (float4 loads) ----------------
__global__ void attn_coef_kernel(const float* __restrict__ feat,
                                 const float* __restrict__ al, const float* __restrict__ ar,
                                 float* __restrict__ el, float* __restrict__ er) {
    int i = blockIdx.x * blockDim.x + threadIdx.x;
    if (i >= N_NODES * HEADS) return;
    int node = i >> 2, h = i & 3;
    const float4* f4 = (const float4*)(feat + (size_t)node * HID + h * HD);
    const float4* a4 = (const float4*)(al + h * HD);
    const float4* r4 = (const float4*)(ar + h * HD);
    float sl = 0.f, sr = 0.f;
    #pragma unroll
    for (int q = 0; q < 6; q++) {
        float4 v = f4[q], a = a4[q], r = r4[q];
        sl += v.x * a.x + v.y * a.y + v.z * a.z + v.w * a.w;
        sr += v.x * r.x + v.y * r.y + v.z * r.z + v.w * r.w;
    }
    el[i] = sl;
    er[i] = sr;
}

// ---------------- aggregation: warp per node ----------------
__global__ void aggregate_kernel(const float* __restrict__ feat,
                                 const int* __restrict__ row_off,
                                 const int* __restrict__ csr_src,
                                 const float* __restrict__ el,
                                 const float* __restrict__ er,
                                 const float* __restrict__ bias,
                                 float* __restrict__ wbuf,
                                 float* __restrict__ out) {
    int warp = (blockIdx.x * blockDim.x + threadIdx.x) >> 5;
    int lane = threadIdx.x & 31;
    if (warp >= N_NODES) return;
    int node = warp;
    int beg = row_off[node], end = row_off[node + 1];
    int deg = end - beg;

    float ern[4];
    #pragma unroll
    for (int h = 0; h < 4; h++) ern[h] = er[node * 4 + h];

    float acc0 = 0.f, acc1 = 0.f, acc2 = 0.f;
    float den[4] = {0.f, 0.f, 0.f, 0.f};

    if (deg <= 32) {
        // ---- fast path ----
        int s = 0;                               // 0 (valid idx) for padding lanes
        float4 e = make_float4(-1e30f, -1e30f, -1e30f, -1e30f);
        if (lane < deg) {
            s = csr_src[beg + lane];
            float4 ev = *(const float4*)&el[s * 4];
            e.x = ev.x + ern[0]; e.x = e.x > 0.f ? e.x : NEG_SLOPE * e.x;
            e.y = ev.y + ern[1]; e.y = e.y > 0.f ? e.y : NEG_SLOPE * e.y;
            e.z = ev.z + ern[2]; e.z = e.z > 0.f ? e.z : NEG_SLOPE * e.z;
            e.w = ev.w + ern[3]; e.w = e.w > 0.f ? e.w : NEG_SLOPE * e.w;
        }
        float m0 = e.x, m1 = e.y, m2 = e.z, m3 = e.w;
        #pragma unroll
        for (int off = 16; off; off >>= 1) {
            m0 = fmaxf(m0, __shfl_xor_sync(FULL, m0, off));
            m1 = fmaxf(m1, __shfl_xor_sync(FULL, m1, off));
            m2 = fmaxf(m2, __shfl_xor_sync(FULL, m2, off));
            m3 = fmaxf(m3, __shfl_xor_sync(FULL, m3, off));
        }
        float4 w = make_float4(0.f, 0.f, 0.f, 0.f);  // 0 for padding lanes
        if (lane < deg) {
            w.x = __expf(e.x - m0);
            w.y = __expf(e.y - m1);
            w.z = __expf(e.z - m2);
            w.w = __expf(e.w - m3);
        }
        den[0] = w.x; den[1] = w.y; den[2] = w.z; den[3] = w.w;
        #pragma unroll
        for (int off = 16; off; off >>= 1) {
            den[0] += __shfl_xor_sync(FULL, den[0], off);
            den[1] += __shfl_xor_sync(FULL, den[1], off);
            den[2] += __shfl_xor_sync(FULL, den[2], off);
            den[3] += __shfl_xor_sync(FULL, den[3], off);
        }
        // pass 2: 4-edge groups, branch-free (padding edges have w==0 -> no effect)
        int degR = (deg + 3) & ~3;
        for (int i = 0; i < degR; i += 4) {
            int s0 = __shfl_sync(FULL, s, i);
            int s1 = __shfl_sync(FULL, s, i + 1);
            int s2 = __shfl_sync(FULL, s, i + 2);
            int s3 = __shfl_sync(FULL, s, i + 3);
            float wx0 = __shfl_sync(FULL, w.x, i),     wy0 = __shfl_sync(FULL, w.y, i);
            float wz0 = __shfl_sync(FULL, w.z, i),     ww0 = __shfl_sync(FULL, w.w, i);
            float wx1 = __shfl_sync(FULL, w.x, i + 1), wy1 = __shfl_sync(FULL, w.y, i + 1);
            float wz1 = __shfl_sync(FULL, w.z, i + 1), ww1 = __shfl_sync(FULL, w.w, i + 1);
            float wx2 = __shfl_sync(FULL, w.x, i + 2), wy2 = __shfl_sync(FULL, w.y, i + 2);
            float wz2 = __shfl_sync(FULL, w.z, i + 2), ww2 = __shfl_sync(FULL, w.w, i + 2);
            float wx3 = __shfl_sync(FULL, w.x, i + 3), wy3 = __shfl_sync(FULL, w.y, i + 3);
            float wz3 = __shfl_sync(FULL, w.z, i + 3), ww3 = __shfl_sync(FULL, w.w, i + 3);
            const float* f0 = feat + (size_t)s0 * 96;
            const float* f1 = feat + (size_t)s1 * 96;
            const float* f2 = feat + (size_t)s2 * 96;
            const float* f3 = feat + (size_t)s3 * 96;
            float a00 = f0[lane], a01 = f0[lane + 32], a02 = f0[lane + 64];
            float a10 = f1[lane], a11 = f1[lane + 32], a12 = f1[lane + 64];
            float a20 = f2[lane], a21 = f2[lane + 32], a22 = f2[lane + 64];
            float a30 = f3[lane], a31 = f3[lane + 32], a32 = f3[lane + 64];
            float wA0 = (lane < 24) ? wx0 : wy0, wB0 = (lane < 16) ? wy0 : wz0, wC0 = (lane < 8) ? wz0 : ww0;
            float wA1 = (lane < 24) ? wx1 : wy1, wB1 = (lane < 16) ? wy1 : wz1, wC1 = (lane < 8) ? wz1 : ww1;
            float wA2 = (lane < 24) ? wx2 : wy2, wB2 = (lane < 16) ? wy2 : wz2, wC2 = (lane < 8) ? wz2 : ww2;
            float wA3 = (lane < 24) ? wx3 : wy3, wB3 = (lane < 16) ? wy3 : wz3, wC3 = (lane < 8) ? wz3 : ww3;
            acc0 += wA0 * a00; acc1 += wB0 * a01; acc2 += wC0 * a02;
            acc0 += wA1 * a10; acc1 += wB1 * a11; acc2 += wC1 * a12;
            acc0 += wA2 * a20; acc1 += wB2 * a21; acc2 += wC2 * a22;
            acc0 += wA3 * a30; acc1 += wB3 * a31; acc2 += wC3 * a32;
        }
    } else {
        // ---- fallback path (rare): via wbuf ----
        float m[4] = {-1e30f, -1e30f, -1e30f, -1e30f};
        for (int i = beg + lane; i < end; i += 32) {
            int s = csr_src[i];
            float4 ev = *(const float4*)&el[s * 4];
            float4 e;
            e.x = ev.x + ern[0]; e.x = e.x > 0.f ? e.x : NEG_SLOPE * e.x; m[0] = fmaxf(m[0], e.x);
            e.y = ev.y + ern[1]; e.y = e.y > 0.f ? e.y : NEG_SLOPE * e.y; m[1] = fmaxf(m[1], e.y);
            e.z = ev.z + ern[2]; e.z = e.z > 0.f ? e.z : NEG_SLOPE * e.z; m[2] = fmaxf(m[2], e.z);
            e.w = ev.w + ern[3]; e.w = e.w > 0.f ? e.w : NEG_SLOPE * e.w; m[3] = fmaxf(m[3], e.w);
            *(float4*)&wbuf[(size_t)i * 4] = e;
        }
        #pragma unroll
        for (int off = 16; off; off >>= 1)
            #pragma unroll
            for (int h = 0; h < 4; h++)
                m[h] = fmaxf(m[h], __shfl_xor_sync(FULL, m[h], off));

        for (int i = beg + lane; i < end; i += 32) {
            float4 e = *(const float4*)&wbuf[(size_t)i * 4];
            float4 w;
            w.x = __expf(e.x - m[0]); den[0] += w.x;
            w.y = __expf(e.y - m[1]); den[1] += w.y;
            w.z = __expf(e.z - m[2]); den[2] += w.z;
            w.w = __expf(e.w - m[3]); den[3] += w.w;
            *(float4*)&wbuf[(size_t)i * 4] = w;
        }
        #pragma unroll
        for (int off = 16; off; off >>= 1)
            #pragma unroll
            for (int h = 0; h < 4; h++)
                den[h] += __shfl_xor_sync(FULL, den[h], off);

        for (int i = beg; i < end; i++) {
            int s = csr_src[i];
            float4 w = *(const float4*)&wbuf[(size_t)i * 4];
            const float* fs = feat + (size_t)s * 96;
            float wA = (lane < 24) ? w.x : w.y;
            float wB = (lane < 16) ? w.y : w.z;
            float wC = (lane < 8)  ? w.z : w.w;
            acc0 += wA * fs[lane];
            acc1 += wB * fs[lane + 32];
            acc2 += wC * fs[lane + 64];
        }
    }

    float inv[4];
    #pragma unroll
    for (int h = 0; h < 4; h++) inv[h] = (deg > 0) ? (1.f / den[h]) : 0.f;
    float iA = (lane < 24) ? inv[0] : inv[1];
    float iB = (lane < 16) ? inv[1] : inv[2];
    float iC = (lane < 8)  ? inv[2] : inv[3];

    float v0 = acc0 * iA + bias[lane];
    float v1 = acc1 * iB + bias[lane + 32];
    float v2 = acc2 * iC + bias[lane + 64];
    v0 = v0 > 0.f ? v0 : expm1f(v0);
    v1 = v1 > 0.f ? v1 : expm1f(v1);
    v2 = v2 > 0.f ? v2 : expm1f(v2);
    out[(size_t)node * 96 + lane]      = v0;
    out[(size_t)node * 96 + lane + 32] = v1;
    out[(size_t)node * 96 + lane + 64] = v2;
}

// ---------------- final mean pool ----------------
__global__ void mean_kernel(const float* __restrict__ h, float* __restrict__ out) {
    int c = threadIdx.x;
    int b = blockIdx.x;
    float s = 0.f;
    for (int r = b; r < N_NODES; r += gridDim.x) s += h[(size_t)r * 96 + c];
    atomicAdd(&out[c], s * (1.f / N_NODES));
}

// ---------------- launch ----------------
extern "C" void kernel_launch(void* const* d_in, const int* in_sizes, int n_in,
                              void* d_out, int out_size) {
    const float* feats = (const float*)d_in[0];
    const int*   src   = (const int*)d_in[1];
    const int*   dst   = (const int*)d_in[2];
    const float* W[3]  = {(const float*)d_in[3],  (const float*)d_in[7],  (const float*)d_in[11]};
    const float* al[3] = {(const float*)d_in[4],  (const float*)d_in[8],  (const float*)d_in[12]};
    const float* ar[3] = {(const float*)d_in[5],  (const float*)d_in[9],  (const float*)d_in[13]};
    const float* bb[3] = {(const float*)d_in[6],  (const float*)d_in[10], (const float*)d_in[14]};

    float *feat, *h0, *h1, *el, *er, *wb;
    int *row_off, *wptr, *csr, *bsum;
    cudaGetSymbolAddress((void**)&feat,    g_feat);
    cudaGetSymbolAddress((void**)&h0,      g_h0);
    cudaGetSymbolAddress((void**)&h1,      g_h1);
    cudaGetSymbolAddress((void**)&el,      g_el);
    cudaGetSymbolAddress((void**)&er,      g_er);
    cudaGetSymbolAddress((void**)&wb,      g_w);
    cudaGetSymbolAddress((void**)&row_off, g_row_off);
    cudaGetSymbolAddress((void**)&wptr,    g_wptr);
    cudaGetSymbolAddress((void**)&csr,     g_csr_src);
    cudaGetSymbolAddress((void**)&bsum,    g_bsum);

    const int SB = 49;  // ceil(50000/1024)
    int gemm_grid = (N_NODES + 127) / 128;

    // idx 0-2: CSR build start
    zero_all_kernel<<<(N_NODES + 255) / 256, 256>>>(wptr, N_NODES, (float*)d_out);
    count_kernel<<<(N_EDGES + 255) / 256, 256>>>(dst, wptr);
    scan1_kernel<<<SB, 1024>>>(wptr, row_off, bsum, N_NODES);
    // idx 3: gemm layer 1 — ncu sampling slot
    gemm_kernel<<<gemm_grid, 512>>>(feats, W[0], feat, N_NODES, 128);
    // idx 4-6: finish CSR
    scan2_kernel<<<1, 64>>>(bsum, SB);
    scan3_kernel<<<SB, 1024>>>(row_off, wptr, bsum, N_NODES, N_EDGES);
    scatter_kernel<<<(N_EDGES + 255) / 256, 256>>>(src, dst, wptr, csr);

    // layer 1 rest
    attn_coef_kernel<<<(N_NODES * HEADS + 255) / 256, 256>>>(feat, al[0], ar[0], el, er);
    aggregate_kernel<<<(N_NODES * 32 + 255) / 256, 256>>>(feat, row_off, csr, el, er,
                                                          bb[0], wb, h0);
    // layers 2, 3
    const float* hin = h0;
    float* houts[3] = {h0, h1, h0};
    for (int l = 1; l < 3; l++) {
        gemm_kernel<<<gemm_grid, 512>>>(hin, W[l], feat, N_NODES, 96);
        attn_coef_kernel<<<(N_NODES * HEADS + 255) / 256, 256>>>(feat, al[l], ar[l], el, er);
        aggregate_kernel<<<(N_NODES * 32 + 255) / 256, 256>>>(feat, row_off, csr, el, er,
                                                              bb[l], wb, houts[l]);
        hin = houts[l];
    }

    mean_kernel<<<64, 96>>>(hin, (float*)d_out);
}